// round 8
// baseline (speedup 1.0000x reference)
#include <cuda_runtime.h>
#include <cuda_fp16.h>
#include <cstdint>

// Lorenz96 via HMMA, flipped GEMM: M=positions, N=channels(40 pad 37), K=240.
// B = W2^T fragments hoisted to registers (150 regs, tile-invariant).
// R8: SPT=8, NT=320 (10 warps), 2 m-tiles/warp, GRID=592 persistent.

#define NT     320
#define GRID   592
#define X      40
#define SPT    8
#define NPOS   (SPT*X)        // 320 positions per tile
#define NTILES 8192           // 65536 / SPT
#define AST    248            // W2h row stride (halves)
#define HTST   56             // hT row stride (halves)
#define HT_SAMP (44*HTST)     // 2464 halves per sample

// smem byte offsets
#define SM_W2H   0            // 40*248*2 = 19840
#define SM_HT    19840        // 8*2464*2 = 39424
#define SM_US    59264        // 8*44*4 = 1408
#define SM_W1    60672        // 1440
#define SM_B1    62112        // 288
#define SM_BW    62400        // 20 float4 = 320
#define SM_COEFF 62720        // 72
#define SM_B3    62792        // 4
#define SM_PART  62800        // 320 f32 = 1280
#define SM_TOTAL 64128

__device__ __forceinline__ uint32_t smem_u32(const void* p) {
    uint32_t a;
    asm("{ .reg .u64 t; cvta.to.shared.u64 t, %1; cvt.u32.u64 %0, t; }" : "=r"(a) : "l"(p));
    return a;
}
__device__ __forceinline__ void ldmatrix_x4(uint32_t& a0, uint32_t& a1, uint32_t& a2, uint32_t& a3,
                                            uint32_t addr) {
    asm volatile("ldmatrix.sync.aligned.m8n8.x4.shared.b16 {%0,%1,%2,%3}, [%4];"
                 : "=r"(a0), "=r"(a1), "=r"(a2), "=r"(a3) : "r"(addr));
}
__device__ __forceinline__ void ldmatrix_x2(uint32_t& a0, uint32_t& a1, uint32_t addr) {
    asm volatile("ldmatrix.sync.aligned.m8n8.x2.shared.b16 {%0,%1}, [%2];"
                 : "=r"(a0), "=r"(a1) : "r"(addr));
}
__device__ __forceinline__ void mma16816(float* c, uint32_t a0, uint32_t a1, uint32_t a2, uint32_t a3,
                                         uint32_t b0, uint32_t b1) {
    asm volatile("mma.sync.aligned.m16n8k16.row.col.f32.f16.f16.f32 "
                 "{%0,%1,%2,%3}, {%4,%5,%6,%7}, {%8,%9}, {%0,%1,%2,%3};"
                 : "+f"(c[0]), "+f"(c[1]), "+f"(c[2]), "+f"(c[3])
                 : "r"(a0), "r"(a1), "r"(a2), "r"(a3), "r"(b0), "r"(b1));
}

__global__ __launch_bounds__(NT, 1)
void l96_flip8_kernel(const float* __restrict__ u,  const float* __restrict__ coeff,
                      const float* __restrict__ W1, const float* __restrict__ b1,
                      const float* __restrict__ W2, const float* __restrict__ b2,
                      const float* __restrict__ W3, const float* __restrict__ b3,
                      float* __restrict__ out)
{
    extern __shared__ char sm[];
    const uint32_t smb = smem_u32(sm);
    const int tid  = threadIdx.x;
    const int wid  = tid >> 5;
    const int lane = tid & 31;

    float*  W1s  = (float*)(sm + SM_W1);
    float*  b1s  = (float*)(sm + SM_B1);
    float*  usf  = (float*)(sm + SM_US);
    float*  part = (float*)(sm + SM_PART);
    float4* bw   = (float4*)(sm + SM_BW);
    __half* W2h  = (__half*)(sm + SM_W2H);
    __half* hTh  = (__half*)(sm + SM_HT);

    // ---- stage weights ----
    for (int i = tid; i < 4960; i += NT) ((uint32_t*)(sm + SM_W2H))[i] = 0;
    for (int i = tid; i < 360;  i += NT) W1s[i] = W1[i];
    for (int i = tid; i < 72;   i += NT) b1s[i] = b1[i];
    for (int i = tid; i < 18;   i += NT) ((float*)(sm + SM_COEFF))[i] = coeff[i];
    if (tid == 0) ((float*)(sm + SM_B3))[0] = b3[0];
    for (int i = tid; i < 20; i += NT) {
        int c = (i >> 2) * 8 + (i & 3) * 2;
        float bx = (c     < 37) ? b2[c]     : 0.f;
        float by = (c + 1 < 37) ? b2[c + 1] : 0.f;
        float wz = (c     < 37) ? W3[c]     : 0.f;
        float ww = (c + 1 < 37) ? W3[c + 1] : 0.f;
        bw[i] = make_float4(bx, by, wz, ww);
    }
    __syncthreads();
    // W2h[co][k=d*48+ci] = W2[co][ci*5+d], rows 37-39 stay zero
    for (int i = tid; i < 37 * 240; i += NT) {
        int co = i / 240, k = i % 240;
        int d = k / 48, ci = k % 48;
        W2h[co * AST + k] = __float2half(W2[co * 240 + ci * 5 + d]);
    }
    __syncthreads();

    // ---- hoist all B = W2^T fragments into registers (tile-invariant) ----
    uint32_t bf[15][5][2];
    {
        const uint32_t bb = smb + SM_W2H +
            (uint32_t)(((lane & 7) * AST + ((lane >> 3) & 1) * 8) * 2);
        #pragma unroll
        for (int kt = 0; kt < 15; kt++)
            #pragma unroll
            for (int nt = 0; nt < 5; nt++)
                ldmatrix_x2(bf[kt][nt][0], bf[kt][nt][1],
                            bb + (uint32_t)(nt * (8 * AST * 2) + kt * 32));
    }

    // ---- per-lane A base addresses for this warp's 2 m-tiles ----
    uint32_t a_base[2];
    #pragma unroll
    for (int mt = 0; mt < 2; mt++) {
        int posg = (wid + 10 * mt) * 16 + (lane & 15);
        int s = posg / X, p = posg % X;
        a_base[mt] = smb + SM_HT +
            (uint32_t)((s * HT_SAMP + p * HTST + ((lane >> 4) << 3)) * 2);
    }

    // ---- conv1 role: 288 active threads, fixed channel, 6 position groups ----
    const int  c1c  = tid % 48;
    const int  grp  = tid / 48;          // 0..5 active, 6 for idle tail
    const bool c1on = (tid < 288);
    float w1r[5], w1g[5], b1v = 0.f, b1g = 0.f;
    if (c1on) {
        b1v = b1s[c1c];
        #pragma unroll
        for (int d = 0; d < 5; d++) w1r[d] = W1s[c1c * 5 + d];
        if (c1c >= 24) {
            b1g = b1s[(c1c + 24)];
            #pragma unroll
            for (int d = 0; d < 5; d++) w1g[d] = W1s[(c1c + 24) * 5 + d];
        }
    }

    for (int tile = blockIdx.x; tile < NTILES; tile += GRID) {
        const size_t gbase = (size_t)tile * NPOS;

        // ---- stage u (8 samples, halo 44) ----
        {
            int s = tid / X, p = tid % X;
            float v = u[gbase + tid];
            float* ur = usf + s * 44;
            ur[p + 2] = v;
            if (p < 2)   ur[p + 42] = v;
            if (p >= 38) ur[p - 38] = v;
        }
        __syncthreads();

        // ---- conv1 + gate -> hT fp16 ----
        if (c1on) {
            #pragma unroll
            for (int j = 0; j < 54; j++) {
                int sp = grp + 6 * j;       // 0..323
                if (sp < NPOS) {
                    int s = sp / X, p = sp % X;
                    const float* ur = usf + s * 44 + p;
                    float u0 = ur[0], u1 = ur[1], u2 = ur[2], u3 = ur[3], u4 = ur[4];
                    float a = b1v;
                    a = fmaf(w1r[0], u0, a); a = fmaf(w1r[1], u1, a); a = fmaf(w1r[2], u2, a);
                    a = fmaf(w1r[3], u3, a); a = fmaf(w1r[4], u4, a);
                    a = fmaxf(a, 0.f);
                    if (c1c >= 24) {
                        float g = b1g;
                        g = fmaf(w1g[0], u0, g); g = fmaf(w1g[1], u1, g); g = fmaf(w1g[2], u2, g);
                        g = fmaf(w1g[3], u3, g); g = fmaf(w1g[4], u4, g);
                        a *= fmaxf(g, 0.f);
                    }
                    __half hv = __float2half(a);
                    __half* ht = hTh + s * HT_SAMP;
                    ht[(p + 2) * HTST + c1c] = hv;
                    if (p < 2)   ht[(p + 42) * HTST + c1c] = hv;
                    if (p >= 38) ht[(p - 38) * HTST + c1c] = hv;
                }
            }
        }
        __syncthreads();

        // ---- GEMM: 2 m-tiles per warp, 15 kt x 5 nt each, B in regs ----
        #pragma unroll
        for (int mt = 0; mt < 2; mt++) {
            float acc[5][4];
            #pragma unroll
            for (int nt = 0; nt < 5; nt++)
                #pragma unroll
                for (int j = 0; j < 4; j++) acc[nt][j] = 0.f;

            #pragma unroll
            for (int kt = 0; kt < 15; kt++) {
                const int d   = kt / 3;
                const int ci0 = (kt % 3) * 16;
                uint32_t a0, a1, a2, a3;
                ldmatrix_x4(a0, a1, a2, a3, a_base[mt] + (uint32_t)((d * HTST + ci0) * 2));
                #pragma unroll
                for (int nt = 0; nt < 5; nt++)
                    mma16816(acc[nt], a0, a1, a2, a3, bf[kt][nt][0], bf[kt][nt][1]);
            }

            // epilogue: relu(acc+b2)*W3, in-thread + quad shfl reduce
            float sum0 = 0.f, sum1 = 0.f;
            #pragma unroll
            for (int nt = 0; nt < 5; nt++) {
                float4 w = bw[nt * 4 + (lane & 3)];
                sum0 += fmaxf(acc[nt][0] + w.x, 0.f) * w.z
                      + fmaxf(acc[nt][1] + w.y, 0.f) * w.w;
                sum1 += fmaxf(acc[nt][2] + w.x, 0.f) * w.z
                      + fmaxf(acc[nt][3] + w.y, 0.f) * w.w;
            }
            sum0 += __shfl_xor_sync(0xFFFFFFFF, sum0, 1);
            sum0 += __shfl_xor_sync(0xFFFFFFFF, sum0, 2);
            sum1 += __shfl_xor_sync(0xFFFFFFFF, sum1, 1);
            sum1 += __shfl_xor_sync(0xFFFFFFFF, sum1, 2);
            if ((lane & 3) == 0) {
                int r = lane >> 2;
                int base = (wid + 10 * mt) * 16;
                part[base + r]     = sum0;
                part[base + r + 8] = sum1;
            }
        }
        __syncthreads();

        // ---- final: stencil head + b3 + conv partial ----
        {
            int s = tid / X, p = tid % X;
            const float* ur = usf + s * 44 + p;
            const float* cf = (const float*)(sm + SM_COEFF);
            float um2 = ur[0], um1 = ur[1], uc = ur[2], up1 = ur[3], up2 = ur[4];
            float o = cf[0];
            o = fmaf(cf[1],  um2,       o);
            o = fmaf(cf[2],  um1,       o);
            o = fmaf(cf[3],  uc,        o);
            o = fmaf(cf[4],  up1,       o);
            o = fmaf(cf[5],  up2,       o);
            o = fmaf(cf[6],  um2 * um2, o);
            o = fmaf(cf[7],  um1 * um1, o);
            o = fmaf(cf[8],  uc  * uc,  o);
            o = fmaf(cf[9],  up1 * up1, o);
            o = fmaf(cf[10], up2 * up2, o);
            o = fmaf(cf[11], um2 * um1, o);
            o = fmaf(cf[12], um1 * uc,  o);
            o = fmaf(cf[13], uc  * up1, o);
            o = fmaf(cf[14], up1 * up2, o);
            o = fmaf(cf[15], um2 * uc,  o);
            o = fmaf(cf[16], um1 * up1, o);
            o = fmaf(cf[17], uc  * up2, o);
            o += ((float*)(sm + SM_B3))[0];
            o += part[tid];
            out[gbase + tid] = o;
        }
        __syncthreads();
    }
}

extern "C" void kernel_launch(void* const* d_in, const int* in_sizes, int n_in,
                              void* d_out, int out_size)
{
    // inputs: 0:t 1:u 2:coeff 3:W1 4:b1 5:W2 6:b2 7:W3 8:b3
    const float* u     = (const float*)d_in[1];
    const float* coeff = (const float*)d_in[2];
    const float* W1    = (const float*)d_in[3];
    const float* b1    = (const float*)d_in[4];
    const float* W2    = (const float*)d_in[5];
    const float* b2    = (const float*)d_in[6];
    const float* W3    = (const float*)d_in[7];
    const float* b3    = (const float*)d_in[8];
    float* out = (float*)d_out;

    cudaFuncSetAttribute(l96_flip8_kernel, cudaFuncAttributeMaxDynamicSharedMemorySize, SM_TOTAL);
    l96_flip8_kernel<<<GRID, NT, SM_TOTAL>>>(u, coeff, W1, b1, W2, b2, W3, b3, out);
}

// round 9
// speedup vs baseline: 1.9515x; 1.9515x over previous
#include <cuda_runtime.h>
#include <cuda_fp16.h>
#include <cstdint>

// Lorenz96 via HMMA (R6 architecture + cheap conv1).
// conv1(1->72,k5,wrap)+gate fp32 -> hT[44][48] fp16 per sample (transposed).
// conv2 GEMM: D[48pad(37)][160] = W2perm[48][240] x B[240][160], B frags via
// ldmatrix from hT (im2col folded, K order d*48+ci).
// R9: conv1 restructured: warp-uniform gating, sliding-window u, per-tile weights.

#define NT     384
#define GRID   296
#define X      40
#define SPT    4
#define NTILES 16384          // 65536 / SPT
#define AST    248            // W2h row stride (halves)
#define HTST   56             // hT row stride (halves)
#define HT_SAMP (44*HTST)     // 2464 halves per sample

// smem byte offsets (all 16B aligned)
#define SM_W2H   0            // 48*248*2 = 23808
#define SM_HT    23808        // 4*2464*2 = 19712
#define SM_US    43520        // 4*44*4 = 704
#define SM_W1    44224        // 1440
#define SM_B1    45664        // 288
#define SM_B2    45952        // 192
#define SM_W3    46144        // 192
#define SM_COEFF 46336        // 72
#define SM_B3    46408        // 4
#define SM_PART  46464        // 12*40*4 = 1920
#define SM_TOTAL 48384

__device__ __forceinline__ uint32_t smem_u32(const void* p) {
    uint32_t a;
    asm("{ .reg .u64 t; cvta.to.shared.u64 t, %1; cvt.u32.u64 %0, t; }" : "=r"(a) : "l"(p));
    return a;
}
__device__ __forceinline__ void ldmatrix_x4(uint32_t& a0, uint32_t& a1, uint32_t& a2, uint32_t& a3,
                                            uint32_t addr) {
    asm volatile("ldmatrix.sync.aligned.m8n8.x4.shared.b16 {%0,%1,%2,%3}, [%4];"
                 : "=r"(a0), "=r"(a1), "=r"(a2), "=r"(a3) : "r"(addr));
}
__device__ __forceinline__ void ldmatrix_x2(uint32_t& a0, uint32_t& a1, uint32_t addr) {
    asm volatile("ldmatrix.sync.aligned.m8n8.x2.shared.b16 {%0,%1}, [%2];"
                 : "=r"(a0), "=r"(a1) : "r"(addr));
}
__device__ __forceinline__ void mma16816(float* c, uint32_t a0, uint32_t a1, uint32_t a2, uint32_t a3,
                                         uint32_t b0, uint32_t b1) {
    asm volatile("mma.sync.aligned.m16n8k16.row.col.f32.f16.f16.f32 "
                 "{%0,%1,%2,%3}, {%4,%5,%6,%7}, {%8,%9}, {%0,%1,%2,%3};"
                 : "+f"(c[0]), "+f"(c[1]), "+f"(c[2]), "+f"(c[3])
                 : "r"(a0), "r"(a1), "r"(a2), "r"(a3), "r"(b0), "r"(b1));
}

__global__ __launch_bounds__(NT, 2)
void l96_hmma3_kernel(const float* __restrict__ u,  const float* __restrict__ coeff,
                      const float* __restrict__ W1, const float* __restrict__ b1,
                      const float* __restrict__ W2, const float* __restrict__ b2,
                      const float* __restrict__ W3, const float* __restrict__ b3,
                      float* __restrict__ out)
{
    extern __shared__ char sm[];
    const uint32_t smb = smem_u32(sm);
    const int tid  = threadIdx.x;
    const int wid  = tid >> 5;
    const int lane = tid & 31;

    float* W1s  = (float*)(sm + SM_W1);
    float* b1s  = (float*)(sm + SM_B1);
    float* b2s  = (float*)(sm + SM_B2);
    float* w3s  = (float*)(sm + SM_W3);
    float* usf  = (float*)(sm + SM_US);
    float* part = (float*)(sm + SM_PART);   // [mw*4+sw][40]
    __half* W2h = (__half*)(sm + SM_W2H);
    __half* hTh = (__half*)(sm + SM_HT);

    // ---- stage weights ----
    for (int i = tid; i < 48 * AST / 2; i += NT) ((uint32_t*)(sm + SM_W2H))[i] = 0;
    for (int i = tid; i < 360; i += NT) W1s[i] = W1[i];
    for (int i = tid; i < 72;  i += NT) b1s[i] = b1[i];
    for (int i = tid; i < 48;  i += NT) {
        b2s[i] = (i < 37) ? b2[i] : 0.f;
        w3s[i] = (i < 37) ? W3[i] : 0.f;
    }
    for (int i = tid; i < 18; i += NT) ((float*)(sm + SM_COEFF))[i] = coeff[i];
    if (tid == 0) ((float*)(sm + SM_B3))[0] = b3[0];
    __syncthreads();
    // W2 with permuted K: W2h[co][d*48+ci] = W2[co][ci*5+d]
    for (int i = tid; i < 37 * 240; i += NT) {
        int co = i / 240, k = i % 240;
        int ci = k / 5, d = k % 5;
        W2h[co * AST + d * 48 + ci] = __float2half(W2[i]);
    }
    __syncthreads();

    // GEMM warp roles
    const int mw = wid >> 2;   // 0..2  M-tile (rows mw*16..+15)
    const int sw = wid & 3;    // 0..3  sample

    // A ldmatrix lane address (k0 byte offset added per kt)
    const uint32_t a_lane = smb + SM_W2H +
        (uint32_t)(((mw * 16 + (lane & 15)) * AST + ((lane >> 4) << 3)) * 2);
    // B lane addresses into hT (halo row = n + d)
    const uint32_t hT_s = smb + SM_HT + (uint32_t)(sw * HT_SAMP * 2);
    const uint32_t b_lane4 = hT_s +
        (uint32_t)((((lane & 7) + ((lane >> 4) & 1) * 8) * HTST + ((lane >> 3) & 1) * 8) * 2);
    const uint32_t b_lane2 = hT_s +
        (uint32_t)(((lane & 7) * HTST + ((lane >> 3) & 1) * 8) * 2);

    // conv1 roles: channel = tid>>3 (warp-uniform gating), 5 consecutive pos/group
    const int c1c = tid >> 3;        // 0..47
    const int p0  = (tid & 7) * 5;   // 0,5,...,35
    const bool gated = (c1c >= 24);

    for (int tile = blockIdx.x; tile < NTILES; tile += GRID) {
        const size_t gbase = (size_t)tile * (SPT * X);

        // ---- stage u (4 samples, halo 44) ----
        if (tid < SPT * X) {
            int s = tid / X, p = tid % X;
            float v = u[gbase + tid];
            float* ur = usf + s * 44;
            ur[p + 2] = v;
            if (p < 2)   ur[p + 42] = v;
            if (p >= 38) ur[p - 38] = v;
        }
        __syncthreads();

        // ---- conv1 + gate -> hT fp16 (sliding window, per-tile weights) ----
        {
            float w1r[5], w1g[5];
            float b1v = b1s[c1c], b1g = 0.f;
            #pragma unroll
            for (int d = 0; d < 5; d++) w1r[d] = W1s[c1c * 5 + d];
            if (gated) {
                b1g = b1s[c1c + 24];
                #pragma unroll
                for (int d = 0; d < 5; d++) w1g[d] = W1s[(c1c + 24) * 5 + d];
            }
            #pragma unroll
            for (int s = 0; s < SPT; s++) {
                const float* ur = usf + s * 44 + p0;
                float uw0 = ur[0], uw1 = ur[1], uw2 = ur[2], uw3 = ur[3];
                __half* ht = hTh + s * HT_SAMP + c1c;
                #pragma unroll
                for (int j = 0; j < 5; j++) {
                    float uw4 = ur[j + 4];
                    float a = b1v;
                    a = fmaf(w1r[0], uw0, a); a = fmaf(w1r[1], uw1, a);
                    a = fmaf(w1r[2], uw2, a); a = fmaf(w1r[3], uw3, a);
                    a = fmaf(w1r[4], uw4, a);
                    a = fmaxf(a, 0.f);
                    if (gated) {
                        float g = b1g;
                        g = fmaf(w1g[0], uw0, g); g = fmaf(w1g[1], uw1, g);
                        g = fmaf(w1g[2], uw2, g); g = fmaf(w1g[3], uw3, g);
                        g = fmaf(w1g[4], uw4, g);
                        a *= fmaxf(g, 0.f);
                    }
                    __half hv = __float2half(a);
                    int p = p0 + j;
                    ht[(p + 2) * HTST] = hv;
                    if (p < 2)   ht[(p + 42) * HTST] = hv;
                    if (p >= 38) ht[(p - 38) * HTST] = hv;
                    uw0 = uw1; uw1 = uw2; uw2 = uw3; uw3 = uw4;
                }
            }
        }
        __syncthreads();

        // ---- GEMM: 15 kt, per kt: A x4 + B 2*x4 + x2, 5 HMMA ----
        float acc[20];
        #pragma unroll
        for (int j = 0; j < 20; j++) acc[j] = 0.f;

        #pragma unroll
        for (int kt = 0; kt < 15; kt++) {
            const int d   = kt / 3;
            const int ci0 = (kt % 3) * 16;
            uint32_t a0, a1, a2, a3;
            ldmatrix_x4(a0, a1, a2, a3, a_lane + (uint32_t)(kt * 32));

            const uint32_t bofs = (uint32_t)(((d * HTST) + ci0) * 2);   // halo row n + d
            uint32_t b0, b1_, b2_, b3_;
            ldmatrix_x4(b0, b1_, b2_, b3_, b_lane4 + bofs);                       // n 0..15
            mma16816(acc + 0, a0, a1, a2, a3, b0, b1_);
            mma16816(acc + 4, a0, a1, a2, a3, b2_, b3_);
            ldmatrix_x4(b0, b1_, b2_, b3_, b_lane4 + bofs + (uint32_t)(16 * HTST * 2)); // n 16..31
            mma16816(acc + 8,  a0, a1, a2, a3, b0, b1_);
            mma16816(acc + 12, a0, a1, a2, a3, b2_, b3_);
            uint32_t c0, c1;
            ldmatrix_x2(c0, c1, b_lane2 + bofs + (uint32_t)(32 * HTST * 2));           // n 32..39
            mma16816(acc + 16, a0, a1, a2, a3, c0, c1);
        }

        // ---- epilogue: relu(acc+b2)*W3, reduce over 16 rows ----
        {
            const int r0 = mw * 16 + (lane >> 2);
            const float b2a = b2s[r0],     w3a = w3s[r0];
            const float b2b = b2s[r0 + 8], w3b = w3s[r0 + 8];
            float* pp = part + (mw * 4 + sw) * 40;
            #pragma unroll
            for (int nt = 0; nt < 5; nt++) {
                float t0 = fmaxf(acc[nt*4+0] + b2a, 0.f) * w3a
                         + fmaxf(acc[nt*4+2] + b2b, 0.f) * w3b;
                float t1 = fmaxf(acc[nt*4+1] + b2a, 0.f) * w3a
                         + fmaxf(acc[nt*4+3] + b2b, 0.f) * w3b;
                #pragma unroll
                for (int ofs = 4; ofs <= 16; ofs <<= 1) {
                    t0 += __shfl_xor_sync(0xFFFFFFFF, t0, ofs);
                    t1 += __shfl_xor_sync(0xFFFFFFFF, t1, ofs);
                }
                if (lane < 4) {
                    pp[nt * 8 + lane * 2]     = t0;
                    pp[nt * 8 + lane * 2 + 1] = t1;
                }
            }
        }
        __syncthreads();

        // ---- final: stencil head + b3 + sum of 3 m-partials ----
        if (tid < SPT * X) {
            int s = tid / X, p = tid % X;
            const float* ur = usf + s * 44 + p;
            const float* cf = (const float*)(sm + SM_COEFF);
            float um2 = ur[0], um1 = ur[1], uc = ur[2], up1 = ur[3], up2 = ur[4];
            float o = cf[0];
            o = fmaf(cf[1],  um2,       o);
            o = fmaf(cf[2],  um1,       o);
            o = fmaf(cf[3],  uc,        o);
            o = fmaf(cf[4],  up1,       o);
            o = fmaf(cf[5],  up2,       o);
            o = fmaf(cf[6],  um2 * um2, o);
            o = fmaf(cf[7],  um1 * um1, o);
            o = fmaf(cf[8],  uc  * uc,  o);
            o = fmaf(cf[9],  up1 * up1, o);
            o = fmaf(cf[10], up2 * up2, o);
            o = fmaf(cf[11], um2 * um1, o);
            o = fmaf(cf[12], um1 * uc,  o);
            o = fmaf(cf[13], uc  * up1, o);
            o = fmaf(cf[14], up1 * up2, o);
            o = fmaf(cf[15], um2 * uc,  o);
            o = fmaf(cf[16], um1 * up1, o);
            o = fmaf(cf[17], uc  * up2, o);
            o += ((float*)(sm + SM_B3))[0];
            o += part[(0 * 4 + s) * 40 + p];
            o += part[(1 * 4 + s) * 40 + p];
            o += part[(2 * 4 + s) * 40 + p];
            out[gbase + tid] = o;
        }
        __syncthreads();
    }
}

extern "C" void kernel_launch(void* const* d_in, const int* in_sizes, int n_in,
                              void* d_out, int out_size)
{
    // inputs: 0:t 1:u 2:coeff 3:W1 4:b1 5:W2 6:b2 7:W3 8:b3
    const float* u     = (const float*)d_in[1];
    const float* coeff = (const float*)d_in[2];
    const float* W1    = (const float*)d_in[3];
    const float* b1    = (const float*)d_in[4];
    const float* W2    = (const float*)d_in[5];
    const float* b2    = (const float*)d_in[6];
    const float* W3    = (const float*)d_in[7];
    const float* b3    = (const float*)d_in[8];
    float* out = (float*)d_out;

    cudaFuncSetAttribute(l96_hmma3_kernel, cudaFuncAttributeMaxDynamicSharedMemorySize, SM_TOTAL);
    l96_hmma3_kernel<<<GRID, NT, SM_TOTAL>>>(u, coeff, W1, b1, W2, b2, W3, b3, out);
}

// round 10
// speedup vs baseline: 2.3290x; 1.1934x over previous
#include <cuda_runtime.h>
#include <cuda_fp16.h>
#include <cstdint>

// Lorenz96 via HMMA. R10: warp = sample, 3 M-tiles per warp (B read once).
// conv1(1->72,k5,wrap)+gate fp32 -> hT[44][48] fp16 per sample (transposed).
// conv2 GEMM per warp: D[48pad(37)][40] = W2perm[48][240] x B[240][40],
// B frags via ldmatrix from hT (im2col folded, K order d*48+ci).

#define NT     256
#define GRID   296
#define X      40
#define SPT    8
#define NPOS   (SPT*X)        // 320
#define NTILES 8192           // 65536 / SPT
#define AST    248            // W2h row stride (halves)
#define HTST   56             // hT row stride (halves)
#define HT_SAMP (44*HTST)     // 2464 halves per sample

// smem byte offsets (16B aligned)
#define SM_W2H   0            // 48*248*2 = 23808
#define SM_HT    23808        // 8*2464*2 = 39424
#define SM_US    63232        // 8*44*4 = 1408
#define SM_W1    64640        // 1440
#define SM_B1    66080        // 288
#define SM_B2    66368        // 192
#define SM_W3    66560        // 192
#define SM_COEFF 66752        // 72
#define SM_B3    66824        // 4+pad
#define SM_PART  66832        // 320*4 = 1280
#define SM_TOTAL 68352

__device__ __forceinline__ uint32_t smem_u32(const void* p) {
    uint32_t a;
    asm("{ .reg .u64 t; cvta.to.shared.u64 t, %1; cvt.u32.u64 %0, t; }" : "=r"(a) : "l"(p));
    return a;
}
__device__ __forceinline__ void ldmatrix_x4(uint32_t& a0, uint32_t& a1, uint32_t& a2, uint32_t& a3,
                                            uint32_t addr) {
    asm volatile("ldmatrix.sync.aligned.m8n8.x4.shared.b16 {%0,%1,%2,%3}, [%4];"
                 : "=r"(a0), "=r"(a1), "=r"(a2), "=r"(a3) : "r"(addr));
}
__device__ __forceinline__ void ldmatrix_x2(uint32_t& a0, uint32_t& a1, uint32_t addr) {
    asm volatile("ldmatrix.sync.aligned.m8n8.x2.shared.b16 {%0,%1}, [%2];"
                 : "=r"(a0), "=r"(a1) : "r"(addr));
}
__device__ __forceinline__ void mma16816(float* c, uint32_t a0, uint32_t a1, uint32_t a2, uint32_t a3,
                                         uint32_t b0, uint32_t b1) {
    asm volatile("mma.sync.aligned.m16n8k16.row.col.f32.f16.f16.f32 "
                 "{%0,%1,%2,%3}, {%4,%5,%6,%7}, {%8,%9}, {%0,%1,%2,%3};"
                 : "+f"(c[0]), "+f"(c[1]), "+f"(c[2]), "+f"(c[3])
                 : "r"(a0), "r"(a1), "r"(a2), "r"(a3), "r"(b0), "r"(b1));
}

__global__ __launch_bounds__(NT, 2)
void l96_ws_kernel(const float* __restrict__ u,  const float* __restrict__ coeff,
                   const float* __restrict__ W1, const float* __restrict__ b1,
                   const float* __restrict__ W2, const float* __restrict__ b2,
                   const float* __restrict__ W3, const float* __restrict__ b3,
                   float* __restrict__ out)
{
    extern __shared__ char sm[];
    const uint32_t smb = smem_u32(sm);
    const int tid  = threadIdx.x;
    const int wid  = tid >> 5;      // warp = sample
    const int lane = tid & 31;

    float* W1s  = (float*)(sm + SM_W1);
    float* b1s  = (float*)(sm + SM_B1);
    float* b2s  = (float*)(sm + SM_B2);
    float* w3s  = (float*)(sm + SM_W3);
    float* usf  = (float*)(sm + SM_US);
    float* part = (float*)(sm + SM_PART);   // [s*40 + p]
    __half* W2h = (__half*)(sm + SM_W2H);
    __half* hTh = (__half*)(sm + SM_HT);

    // ---- stage weights ----
    for (int i = tid; i < 48 * AST / 2; i += NT) ((uint32_t*)(sm + SM_W2H))[i] = 0;
    for (int i = tid; i < 360; i += NT) W1s[i] = W1[i];
    for (int i = tid; i < 72;  i += NT) b1s[i] = b1[i];
    for (int i = tid; i < 48;  i += NT) {
        b2s[i] = (i < 37) ? b2[i] : 0.f;
        w3s[i] = (i < 37) ? W3[i] : 0.f;
    }
    for (int i = tid; i < 18; i += NT) ((float*)(sm + SM_COEFF))[i] = coeff[i];
    if (tid == 0) ((float*)(sm + SM_B3))[0] = b3[0];
    __syncthreads();
    // W2 with permuted K: W2h[co][d*48+ci] = W2[co][ci*5+d]
    for (int i = tid; i < 37 * 240; i += NT) {
        int co = i / 240, k = i % 240;
        int ci = k / 5, d = k % 5;
        W2h[co * AST + d * 48 + ci] = __float2half(W2[i]);
    }
    __syncthreads();

    // A ldmatrix lane addresses, one per m-tile
    uint32_t a_lane[3];
    #pragma unroll
    for (int mt = 0; mt < 3; mt++)
        a_lane[mt] = smb + SM_W2H +
            (uint32_t)(((mt * 16 + (lane & 15)) * AST + ((lane >> 4) << 3)) * 2);
    // B lane addresses into this warp's sample (halo row = n + d)
    const uint32_t hT_s = smb + SM_HT + (uint32_t)(wid * HT_SAMP * 2);
    const uint32_t b_lane4 = hT_s +
        (uint32_t)((((lane & 7) + ((lane >> 4) & 1) * 8) * HTST + ((lane >> 3) & 1) * 8) * 2);
    const uint32_t b_lane2 = hT_s +
        (uint32_t)(((lane & 7) * HTST + ((lane >> 3) & 1) * 8) * 2);

    // conv1 roles: group g = tid&7 (5 consecutive positions), ch = tid>>3 (+32 pass 2)
    const int p0c = (tid & 7) * 5;
    const int ch1 = tid >> 3;            // 0..31

    for (int tile = blockIdx.x; tile < NTILES; tile += GRID) {
        const size_t gbase = (size_t)tile * NPOS;

        // ---- stage u (8 samples, halo 44) ----
        for (int i = tid; i < NPOS; i += NT) {
            int s = i / X, p = i % X;
            float v = u[gbase + i];
            float* ur = usf + s * 44;
            ur[p + 2] = v;
            if (p < 2)   ur[p + 42] = v;
            if (p >= 38) ur[p - 38] = v;
        }
        __syncthreads();

        // ---- conv1 + gate -> hT fp16 (two channel passes, warp-uniform gating) ----
        #pragma unroll
        for (int pass = 0; pass < 2; pass++) {
            const int ch = ch1 + pass * 32;
            if (ch < 48) {
                const bool gated = (ch >= 24);
                float w1r[5], w1g[5];
                float b1v = b1s[ch], b1g = 0.f;
                #pragma unroll
                for (int d = 0; d < 5; d++) w1r[d] = W1s[ch * 5 + d];
                if (gated) {
                    b1g = b1s[ch + 24];
                    #pragma unroll
                    for (int d = 0; d < 5; d++) w1g[d] = W1s[(ch + 24) * 5 + d];
                }
                #pragma unroll
                for (int s = 0; s < SPT; s++) {
                    const float* ur = usf + s * 44 + p0c;
                    float uw0 = ur[0], uw1 = ur[1], uw2 = ur[2], uw3 = ur[3];
                    __half* ht = hTh + s * HT_SAMP + ch;
                    #pragma unroll
                    for (int j = 0; j < 5; j++) {
                        float uw4 = ur[j + 4];
                        float a = b1v;
                        a = fmaf(w1r[0], uw0, a); a = fmaf(w1r[1], uw1, a);
                        a = fmaf(w1r[2], uw2, a); a = fmaf(w1r[3], uw3, a);
                        a = fmaf(w1r[4], uw4, a);
                        a = fmaxf(a, 0.f);
                        if (gated) {
                            float g = b1g;
                            g = fmaf(w1g[0], uw0, g); g = fmaf(w1g[1], uw1, g);
                            g = fmaf(w1g[2], uw2, g); g = fmaf(w1g[3], uw3, g);
                            g = fmaf(w1g[4], uw4, g);
                            a *= fmaxf(g, 0.f);
                        }
                        __half hv = __float2half(a);
                        int p = p0c + j;
                        ht[(p + 2) * HTST] = hv;
                        if (p < 2)   ht[(p + 42) * HTST] = hv;
                        if (p >= 38) ht[(p - 38) * HTST] = hv;
                        uw0 = uw1; uw1 = uw2; uw2 = uw3; uw3 = uw4;
                    }
                }
            }
        }
        __syncthreads();

        // ---- GEMM: per kt load B once, 3 A tiles, 15 HMMA ----
        float acc[3][20];
        #pragma unroll
        for (int mt = 0; mt < 3; mt++)
            #pragma unroll
            for (int j = 0; j < 20; j++) acc[mt][j] = 0.f;

        #pragma unroll
        for (int kt = 0; kt < 15; kt++) {
            const int d   = kt / 3;
            const int ci0 = (kt % 3) * 16;
            const uint32_t bofs = (uint32_t)(((d * HTST) + ci0) * 2);   // halo row n + d

            uint32_t b0, b1_, b2_, b3_;
            ldmatrix_x4(b0, b1_, b2_, b3_, b_lane4 + bofs);                          // n 0..15
            uint32_t e0, e1, e2, e3;
            ldmatrix_x4(e0, e1, e2, e3, b_lane4 + bofs + (uint32_t)(16 * HTST * 2)); // n 16..31
            uint32_t f0, f1;
            ldmatrix_x2(f0, f1, b_lane2 + bofs + (uint32_t)(32 * HTST * 2));         // n 32..39

            #pragma unroll
            for (int mt = 0; mt < 3; mt++) {
                uint32_t a0, a1, a2, a3;
                ldmatrix_x4(a0, a1, a2, a3, a_lane[mt] + (uint32_t)(kt * 32));
                mma16816(acc[mt] + 0,  a0, a1, a2, a3, b0, b1_);
                mma16816(acc[mt] + 4,  a0, a1, a2, a3, b2_, b3_);
                mma16816(acc[mt] + 8,  a0, a1, a2, a3, e0, e1);
                mma16816(acc[mt] + 12, a0, a1, a2, a3, e2, e3);
                mma16816(acc[mt] + 16, a0, a1, a2, a3, f0, f1);
            }
        }

        // ---- epilogue: relu(acc+b2)*W3, sum 6 rows in-thread, shfl over row-groups ----
        {
            const int r = lane >> 2;
            float b2v[6], w3v[6];
            #pragma unroll
            for (int mt = 0; mt < 3; mt++) {
                b2v[mt*2]   = b2s[mt*16 + r];     w3v[mt*2]   = w3s[mt*16 + r];
                b2v[mt*2+1] = b2s[mt*16 + r + 8]; w3v[mt*2+1] = w3s[mt*16 + r + 8];
            }
            #pragma unroll
            for (int nt = 0; nt < 5; nt++) {
                float t0 = 0.f, t1 = 0.f;
                #pragma unroll
                for (int mt = 0; mt < 3; mt++) {
                    t0 += fmaxf(acc[mt][nt*4+0] + b2v[mt*2],   0.f) * w3v[mt*2]
                        + fmaxf(acc[mt][nt*4+2] + b2v[mt*2+1], 0.f) * w3v[mt*2+1];
                    t1 += fmaxf(acc[mt][nt*4+1] + b2v[mt*2],   0.f) * w3v[mt*2]
                        + fmaxf(acc[mt][nt*4+3] + b2v[mt*2+1], 0.f) * w3v[mt*2+1];
                }
                #pragma unroll
                for (int ofs = 4; ofs <= 16; ofs <<= 1) {
                    t0 += __shfl_xor_sync(0xFFFFFFFF, t0, ofs);
                    t1 += __shfl_xor_sync(0xFFFFFFFF, t1, ofs);
                }
                if (lane < 4) {
                    part[wid * 40 + nt * 8 + lane * 2]     = t0;
                    part[wid * 40 + nt * 8 + lane * 2 + 1] = t1;
                }
            }
        }
        __syncthreads();

        // ---- final: stencil head + b3 + conv partial ----
        for (int i = tid; i < NPOS; i += NT) {
            int s = i / X, p = i % X;
            const float* ur = usf + s * 44 + p;
            const float* cf = (const float*)(sm + SM_COEFF);
            float um2 = ur[0], um1 = ur[1], uc = ur[2], up1 = ur[3], up2 = ur[4];
            float o = cf[0];
            o = fmaf(cf[1],  um2,       o);
            o = fmaf(cf[2],  um1,       o);
            o = fmaf(cf[3],  uc,        o);
            o = fmaf(cf[4],  up1,       o);
            o = fmaf(cf[5],  up2,       o);
            o = fmaf(cf[6],  um2 * um2, o);
            o = fmaf(cf[7],  um1 * um1, o);
            o = fmaf(cf[8],  uc  * uc,  o);
            o = fmaf(cf[9],  up1 * up1, o);
            o = fmaf(cf[10], up2 * up2, o);
            o = fmaf(cf[11], um2 * um1, o);
            o = fmaf(cf[12], um1 * uc,  o);
            o = fmaf(cf[13], uc  * up1, o);
            o = fmaf(cf[14], up1 * up2, o);
            o = fmaf(cf[15], um2 * uc,  o);
            o = fmaf(cf[16], um1 * up1, o);
            o = fmaf(cf[17], uc  * up2, o);
            o += ((float*)(sm + SM_B3))[0];
            o += part[i];
            out[gbase + i] = o;
        }
        __syncthreads();
    }
}

extern "C" void kernel_launch(void* const* d_in, const int* in_sizes, int n_in,
                              void* d_out, int out_size)
{
    // inputs: 0:t 1:u 2:coeff 3:W1 4:b1 5:W2 6:b2 7:W3 8:b3
    const float* u     = (const float*)d_in[1];
    const float* coeff = (const float*)d_in[2];
    const float* W1    = (const float*)d_in[3];
    const float* b1    = (const float*)d_in[4];
    const float* W2    = (const float*)d_in[5];
    const float* b2    = (const float*)d_in[6];
    const float* W3    = (const float*)d_in[7];
    const float* b3    = (const float*)d_in[8];
    float* out = (float*)d_out;

    cudaFuncSetAttribute(l96_ws_kernel, cudaFuncAttributeMaxDynamicSharedMemorySize, SM_TOTAL);
    l96_ws_kernel<<<GRID, NT, SM_TOTAL>>>(u, coeff, W1, b1, W2, b2, W3, b3, out);
}

// round 11
// speedup vs baseline: 3.0612x; 1.3144x over previous
#include <cuda_runtime.h>
#include <cuda_fp16.h>
#include <cstdint>

// Lorenz96, all-tensor: R10 GEMM (warp=sample, 3 M-tiles, B once) + conv1 as HMMA.
// conv1: pre[80pad(72)][40] = W1pad[80][16] x uB[16][40] per sample; gate is
// thread-local (c and c+24 same thread); bias fp32, relu/gate, store h fp16 -> hT.
// conv2 GEMM per warp: D[48pad(37)][40] = W2perm[48][240] x B[240][40] via ldmatrix.

#define NT     256
#define GRID   296
#define X      40
#define SPT    8
#define NPOS   (SPT*X)        // 320
#define NTILES 8192           // 65536 / SPT
#define AST    248            // W2h row stride (halves)
#define HTST   56             // hT row stride (halves)
#define HT_SAMP (44*HTST)     // 2464 halves per sample
#define A1ST   24             // W1A row stride (halves), 48B
#define UBST   40             // uB row stride (halves), 80B
#define UB_SAMP (40*UBST)     // 1600 halves per sample

// smem byte offsets (16B aligned)
#define SM_W2H   0            // 48*248*2 = 23808
#define SM_HT    23808        // 8*2464*2 = 39424 -> 63232
#define SM_UB    63232        // 8*1600*2 = 25600 -> 88832
#define SM_W1A   88832        // 80*24*2 = 3840 -> 92672
#define SM_US    92672        // 8*44*4 = 1408 -> 94080
#define SM_B1    94080        // 288
#define SM_B2    94368        // 192
#define SM_W3    94560        // 192
#define SM_COEFF 94752        // 72
#define SM_B3    94824        // 8
#define SM_PART  94832        // 1280
#define SM_TOTAL 96112

__device__ __forceinline__ uint32_t smem_u32(const void* p) {
    uint32_t a;
    asm("{ .reg .u64 t; cvta.to.shared.u64 t, %1; cvt.u32.u64 %0, t; }" : "=r"(a) : "l"(p));
    return a;
}
__device__ __forceinline__ void ldmatrix_x4(uint32_t& a0, uint32_t& a1, uint32_t& a2, uint32_t& a3,
                                            uint32_t addr) {
    asm volatile("ldmatrix.sync.aligned.m8n8.x4.shared.b16 {%0,%1,%2,%3}, [%4];"
                 : "=r"(a0), "=r"(a1), "=r"(a2), "=r"(a3) : "r"(addr));
}
__device__ __forceinline__ void ldmatrix_x2(uint32_t& a0, uint32_t& a1, uint32_t addr) {
    asm volatile("ldmatrix.sync.aligned.m8n8.x2.shared.b16 {%0,%1}, [%2];"
                 : "=r"(a0), "=r"(a1) : "r"(addr));
}
__device__ __forceinline__ void mma16816(float* c, uint32_t a0, uint32_t a1, uint32_t a2, uint32_t a3,
                                         uint32_t b0, uint32_t b1) {
    asm volatile("mma.sync.aligned.m16n8k16.row.col.f32.f16.f16.f32 "
                 "{%0,%1,%2,%3}, {%4,%5,%6,%7}, {%8,%9}, {%0,%1,%2,%3};"
                 : "+f"(c[0]), "+f"(c[1]), "+f"(c[2]), "+f"(c[3])
                 : "r"(a0), "r"(a1), "r"(a2), "r"(a3), "r"(b0), "r"(b1));
}

__global__ __launch_bounds__(NT, 2)
void l96_tc2_kernel(const float* __restrict__ u,  const float* __restrict__ coeff,
                    const float* __restrict__ W1, const float* __restrict__ b1,
                    const float* __restrict__ W2, const float* __restrict__ b2,
                    const float* __restrict__ W3, const float* __restrict__ b3,
                    float* __restrict__ out)
{
    extern __shared__ char sm[];
    const uint32_t smb = smem_u32(sm);
    const int tid  = threadIdx.x;
    const int wid  = tid >> 5;      // warp = sample
    const int lane = tid & 31;

    float* b1s  = (float*)(sm + SM_B1);
    float* b2s  = (float*)(sm + SM_B2);
    float* w3s  = (float*)(sm + SM_W3);
    float* usf  = (float*)(sm + SM_US);
    float* part = (float*)(sm + SM_PART);   // [s*40 + p]
    __half* W2h = (__half*)(sm + SM_W2H);
    __half* W1A = (__half*)(sm + SM_W1A);
    __half* uBh = (__half*)(sm + SM_UB);
    __half* hTh = (__half*)(sm + SM_HT);

    // ---- stage weights (once) ----
    for (int i = tid; i < 48 * AST / 2; i += NT) ((uint32_t*)(sm + SM_W2H))[i] = 0;
    for (int i = tid; i < 80 * A1ST / 2; i += NT) ((uint32_t*)(sm + SM_W1A))[i] = 0;
    for (int i = tid; i < 8 * UB_SAMP / 2; i += NT) ((uint32_t*)(sm + SM_UB))[i] = 0;
    for (int i = tid; i < 72;  i += NT) b1s[i] = b1[i];
    for (int i = tid; i < 48;  i += NT) {
        b2s[i] = (i < 37) ? b2[i] : 0.f;
        w3s[i] = (i < 37) ? W3[i] : 0.f;
    }
    for (int i = tid; i < 18; i += NT) ((float*)(sm + SM_COEFF))[i] = coeff[i];
    if (tid == 0) ((float*)(sm + SM_B3))[0] = b3[0];
    __syncthreads();
    // W2 with permuted K: W2h[co][d*48+ci] = W2[co][ci*5+d]
    for (int i = tid; i < 37 * 240; i += NT) {
        int co = i / 240, k = i % 240;
        int ci = k / 5, d = k % 5;
        W2h[co * AST + d * 48 + ci] = __float2half(W2[i]);
    }
    // W1A[c][k] = W1[c][k], k<5, c<72 (rest stays zero)
    for (int i = tid; i < 72 * 5; i += NT) {
        int c = i / 5, k = i % 5;
        W1A[c * A1ST + k] = __float2half(W1[i]);
    }
    __syncthreads();

    // conv2 A ldmatrix lane addresses, one per m-tile
    uint32_t a_lane[3];
    #pragma unroll
    for (int mt = 0; mt < 3; mt++)
        a_lane[mt] = smb + SM_W2H +
            (uint32_t)(((mt * 16 + (lane & 15)) * AST + ((lane >> 4) << 3)) * 2);
    // conv2 B lane addresses into this warp's sample (halo row = n + d)
    const uint32_t hT_s = smb + SM_HT + (uint32_t)(wid * HT_SAMP * 2);
    const uint32_t b_lane4 = hT_s +
        (uint32_t)((((lane & 7) + ((lane >> 4) & 1) * 8) * HTST + ((lane >> 3) & 1) * 8) * 2);
    const uint32_t b_lane2 = hT_s +
        (uint32_t)(((lane & 7) * HTST + ((lane >> 3) & 1) * 8) * 2);
    // conv1 A / B lane addresses
    const uint32_t a1_lane = smb + SM_W1A +
        (uint32_t)(((lane & 15) * A1ST + ((lane >> 4) << 3)) * 2);
    const uint32_t ub_lane = smb + SM_UB +
        (uint32_t)((wid * UB_SAMP + (lane & 7) * UBST + ((lane >> 3) & 1) * 8) * 2);

    const int g = lane >> 2;            // row within 8-group
    const int q = lane & 3;             // col pair

    for (int tile = blockIdx.x; tile < NTILES; tile += GRID) {
        const size_t gbase = (size_t)tile * NPOS;

        // ---- stage u: fp32 halo (stencil) + fp16 im2col uB ----
        for (int i = tid; i < NPOS; i += NT) {
            int s = i / X, p = i % X;
            float v = u[gbase + i];
            float* ur = usf + s * 44;
            ur[p + 2] = v;
            if (p < 2)   ur[p + 42] = v;
            if (p >= 38) ur[p - 38] = v;
            __half hv = __float2half(v);
            __half* ub = uBh + s * UB_SAMP;
            #pragma unroll
            for (int d = 0; d < 5; d++) {
                int row = p - d + 2;
                row += (row < 0) ? X : 0;
                row -= (row >= X) ? X : 0;
                ub[row * UBST + d] = hv;
            }
        }
        __syncthreads();

        // ---- conv1 via HMMA: pre[80][40] = W1A[80][16] x uB[16][40] ----
        {
            // bias values for this thread's channels (transient)
            float bb[9];
            #pragma unroll
            for (int j = 0; j < 9; j++) bb[j] = b1s[j * 8 + g];
            // A fragments (5 m-tiles, K=16)
            uint32_t af[5][4];
            #pragma unroll
            for (int mt = 0; mt < 5; mt++)
                ldmatrix_x4(af[mt][0], af[mt][1], af[mt][2], af[mt][3],
                            a1_lane + (uint32_t)(mt * 16 * A1ST * 2));

            __half* ht = hTh + wid * HT_SAMP;
            #pragma unroll
            for (int nt = 0; nt < 5; nt++) {
                uint32_t ub0, ub1;
                ldmatrix_x2(ub0, ub1, ub_lane + (uint32_t)(nt * 8 * UBST * 2));
                float acc1[5][4];
                #pragma unroll
                for (int mt = 0; mt < 5; mt++) {
                    #pragma unroll
                    for (int j = 0; j < 4; j++) acc1[mt][j] = 0.f;
                    mma16816(acc1[mt], af[mt][0], af[mt][1], af[mt][2], af[mt][3], ub0, ub1);
                }
                // epilogue: bias + relu + gate, store h (fp16) for 6 ch x 2 cols
                #pragma unroll
                for (int col = 0; col < 2; col++) {
                    int p = nt * 8 + q * 2 + col;
                    float h0  = fmaxf(acc1[0][col]     + bb[0], 0.f);           // ch g
                    float h8  = fmaxf(acc1[0][col + 2] + bb[1], 0.f);           // ch g+8
                    float h16 = fmaxf(acc1[1][col]     + bb[2], 0.f);           // ch 16+g
                    float h24 = fmaxf(acc1[1][col + 2] + bb[3], 0.f)
                              * fmaxf(acc1[3][col]     + bb[6], 0.f);           // ch 24+g
                    float h32 = fmaxf(acc1[2][col]     + bb[4], 0.f)
                              * fmaxf(acc1[3][col + 2] + bb[7], 0.f);           // ch 32+g
                    float h40 = fmaxf(acc1[2][col + 2] + bb[5], 0.f)
                              * fmaxf(acc1[4][col]     + bb[8], 0.f);           // ch 40+g
                    __half* hp = ht + (p + 2) * HTST;
                    hp[g]      = __float2half(h0);
                    hp[g + 8]  = __float2half(h8);
                    hp[g + 16] = __float2half(h16);
                    hp[g + 24] = __float2half(h24);
                    hp[g + 32] = __float2half(h32);
                    hp[g + 40] = __float2half(h40);
                    if (p < 2 || p >= 38) {
                        __half* hq = ht + ((p < 2) ? (p + 42) : (p - 38)) * HTST;
                        hq[g]      = __float2half(h0);
                        hq[g + 8]  = __float2half(h8);
                        hq[g + 16] = __float2half(h16);
                        hq[g + 24] = __float2half(h24);
                        hq[g + 32] = __float2half(h32);
                        hq[g + 40] = __float2half(h40);
                    }
                }
            }
        }
        __syncthreads();

        // ---- conv2 GEMM: per kt load B once, 3 A tiles, 15 HMMA ----
        float acc[3][20];
        #pragma unroll
        for (int mt = 0; mt < 3; mt++)
            #pragma unroll
            for (int j = 0; j < 20; j++) acc[mt][j] = 0.f;

        #pragma unroll
        for (int kt = 0; kt < 15; kt++) {
            const int d   = kt / 3;
            const int ci0 = (kt % 3) * 16;
            const uint32_t bofs = (uint32_t)(((d * HTST) + ci0) * 2);   // halo row n + d

            uint32_t b0, b1_, b2_, b3_;
            ldmatrix_x4(b0, b1_, b2_, b3_, b_lane4 + bofs);                          // n 0..15
            uint32_t e0, e1, e2, e3;
            ldmatrix_x4(e0, e1, e2, e3, b_lane4 + bofs + (uint32_t)(16 * HTST * 2)); // n 16..31
            uint32_t f0, f1;
            ldmatrix_x2(f0, f1, b_lane2 + bofs + (uint32_t)(32 * HTST * 2));         // n 32..39

            #pragma unroll
            for (int mt = 0; mt < 3; mt++) {
                uint32_t a0, a1, a2, a3;
                ldmatrix_x4(a0, a1, a2, a3, a_lane[mt] + (uint32_t)(kt * 32));
                mma16816(acc[mt] + 0,  a0, a1, a2, a3, b0, b1_);
                mma16816(acc[mt] + 4,  a0, a1, a2, a3, b2_, b3_);
                mma16816(acc[mt] + 8,  a0, a1, a2, a3, e0, e1);
                mma16816(acc[mt] + 12, a0, a1, a2, a3, e2, e3);
                mma16816(acc[mt] + 16, a0, a1, a2, a3, f0, f1);
            }
        }

        // ---- epilogue: relu(acc+b2)*W3, sum 6 rows in-thread, shfl reduce ----
        {
            float b2v[6], w3v[6];
            #pragma unroll
            for (int mt = 0; mt < 3; mt++) {
                b2v[mt*2]   = b2s[mt*16 + g];     w3v[mt*2]   = w3s[mt*16 + g];
                b2v[mt*2+1] = b2s[mt*16 + g + 8]; w3v[mt*2+1] = w3s[mt*16 + g + 8];
            }
            #pragma unroll
            for (int nt = 0; nt < 5; nt++) {
                float t0 = 0.f, t1 = 0.f;
                #pragma unroll
                for (int mt = 0; mt < 3; mt++) {
                    t0 += fmaxf(acc[mt][nt*4+0] + b2v[mt*2],   0.f) * w3v[mt*2]
                        + fmaxf(acc[mt][nt*4+2] + b2v[mt*2+1], 0.f) * w3v[mt*2+1];
                    t1 += fmaxf(acc[mt][nt*4+1] + b2v[mt*2],   0.f) * w3v[mt*2]
                        + fmaxf(acc[mt][nt*4+3] + b2v[mt*2+1], 0.f) * w3v[mt*2+1];
                }
                #pragma unroll
                for (int ofs = 4; ofs <= 16; ofs <<= 1) {
                    t0 += __shfl_xor_sync(0xFFFFFFFF, t0, ofs);
                    t1 += __shfl_xor_sync(0xFFFFFFFF, t1, ofs);
                }
                if (lane < 4) {
                    part[wid * 40 + nt * 8 + lane * 2]     = t0;
                    part[wid * 40 + nt * 8 + lane * 2 + 1] = t1;
                }
            }
        }
        __syncthreads();

        // ---- final: stencil head (fp32) + b3 + conv partial ----
        for (int i = tid; i < NPOS; i += NT) {
            int s = i / X, p = i % X;
            const float* ur = usf + s * 44 + p;
            const float* cf = (const float*)(sm + SM_COEFF);
            float um2 = ur[0], um1 = ur[1], uc = ur[2], up1 = ur[3], up2 = ur[4];
            float o = cf[0];
            o = fmaf(cf[1],  um2,       o);
            o = fmaf(cf[2],  um1,       o);
            o = fmaf(cf[3],  uc,        o);
            o = fmaf(cf[4],  up1,       o);
            o = fmaf(cf[5],  up2,       o);
            o = fmaf(cf[6],  um2 * um2, o);
            o = fmaf(cf[7],  um1 * um1, o);
            o = fmaf(cf[8],  uc  * uc,  o);
            o = fmaf(cf[9],  up1 * up1, o);
            o = fmaf(cf[10], up2 * up2, o);
            o = fmaf(cf[11], um2 * um1, o);
            o = fmaf(cf[12], um1 * uc,  o);
            o = fmaf(cf[13], uc  * up1, o);
            o = fmaf(cf[14], up1 * up2, o);
            o = fmaf(cf[15], um2 * uc,  o);
            o = fmaf(cf[16], um1 * up1, o);
            o = fmaf(cf[17], uc  * up2, o);
            o += ((float*)(sm + SM_B3))[0];
            o += part[i];
            out[gbase + i] = o;
        }
        __syncthreads();
    }
}

extern "C" void kernel_launch(void* const* d_in, const int* in_sizes, int n_in,
                              void* d_out, int out_size)
{
    // inputs: 0:t 1:u 2:coeff 3:W1 4:b1 5:W2 6:b2 7:W3 8:b3
    const float* u     = (const float*)d_in[1];
    const float* coeff = (const float*)d_in[2];
    const float* W1    = (const float*)d_in[3];
    const float* b1    = (const float*)d_in[4];
    const float* W2    = (const float*)d_in[5];
    const float* b2    = (const float*)d_in[6];
    const float* W3    = (const float*)d_in[7];
    const float* b3    = (const float*)d_in[8];
    float* out = (float*)d_out;

    cudaFuncSetAttribute(l96_tc2_kernel, cudaFuncAttributeMaxDynamicSharedMemorySize, SM_TOTAL);
    l96_tc2_kernel<<<GRID, NT, SM_TOTAL>>>(u, coeff, W1, b1, W2, b2, W3, b3, out);
}

// round 12
// speedup vs baseline: 3.2238x; 1.0531x over previous
#include <cuda_runtime.h>
#include <cuda_fp16.h>
#include <cstdint>

// Lorenz96, all-tensor, barrier-free main loop (R12).
// warp = sample end-to-end: stage u, conv1 HMMA (pre[80]=W1pad x uB[16][40]),
// gate in-thread, hT fp16, conv2 HMMA (D[48pad]=W2perm x B[240][40] via
// ldmatrix im2col), epilogue reduce, stencil head, store. Only __syncwarp.

#define NT     256
#define GRID   296
#define X      40
#define SPT    8
#define NPOS   (SPT*X)        // 320
#define NTILES 8192           // 65536 / SPT
#define AST    248            // W2h row stride (halves)
#define HTST   56             // hT row stride (halves)
#define HT_SAMP (44*HTST)     // 2464 halves per sample
#define A1ST   24             // W1A row stride (halves)
#define UBST   40             // uB row stride (halves)
#define UB_SAMP (40*UBST)     // 1600 halves per sample

// smem byte offsets (16B aligned)
#define SM_W2H   0            // 23808
#define SM_HT    23808        // 39424 -> 63232
#define SM_UB    63232        // 25600 -> 88832
#define SM_W1A   88832        // 3840 -> 92672
#define SM_US    92672        // 1408 -> 94080
#define SM_B1    94080        // 288
#define SM_B2    94368        // 192
#define SM_W3    94560        // 192
#define SM_COEFF 94752        // 72
#define SM_B3    94824        // 8
#define SM_PART  94832        // 1280
#define SM_TOTAL 96112

__device__ __forceinline__ uint32_t smem_u32(const void* p) {
    uint32_t a;
    asm("{ .reg .u64 t; cvta.to.shared.u64 t, %1; cvt.u32.u64 %0, t; }" : "=r"(a) : "l"(p));
    return a;
}
__device__ __forceinline__ void ldmatrix_x4(uint32_t& a0, uint32_t& a1, uint32_t& a2, uint32_t& a3,
                                            uint32_t addr) {
    asm volatile("ldmatrix.sync.aligned.m8n8.x4.shared.b16 {%0,%1,%2,%3}, [%4];"
                 : "=r"(a0), "=r"(a1), "=r"(a2), "=r"(a3) : "r"(addr));
}
__device__ __forceinline__ void ldmatrix_x2(uint32_t& a0, uint32_t& a1, uint32_t addr) {
    asm volatile("ldmatrix.sync.aligned.m8n8.x2.shared.b16 {%0,%1}, [%2];"
                 : "=r"(a0), "=r"(a1) : "r"(addr));
}
__device__ __forceinline__ void mma16816(float* c, uint32_t a0, uint32_t a1, uint32_t a2, uint32_t a3,
                                         uint32_t b0, uint32_t b1) {
    asm volatile("mma.sync.aligned.m16n8k16.row.col.f32.f16.f16.f32 "
                 "{%0,%1,%2,%3}, {%4,%5,%6,%7}, {%8,%9}, {%0,%1,%2,%3};"
                 : "+f"(c[0]), "+f"(c[1]), "+f"(c[2]), "+f"(c[3])
                 : "r"(a0), "r"(a1), "r"(a2), "r"(a3), "r"(b0), "r"(b1));
}

__global__ __launch_bounds__(NT, 2)
void l96_bf_kernel(const float* __restrict__ u,  const float* __restrict__ coeff,
                   const float* __restrict__ W1, const float* __restrict__ b1,
                   const float* __restrict__ W2, const float* __restrict__ b2,
                   const float* __restrict__ W3, const float* __restrict__ b3,
                   float* __restrict__ out)
{
    extern __shared__ char sm[];
    const uint32_t smb = smem_u32(sm);
    const int tid  = threadIdx.x;
    const int wid  = tid >> 5;      // warp = sample
    const int lane = tid & 31;

    float* b1s  = (float*)(sm + SM_B1);
    float* b2s  = (float*)(sm + SM_B2);
    float* w3s  = (float*)(sm + SM_W3);
    float* usf  = (float*)(sm + SM_US);
    float* part = (float*)(sm + SM_PART);
    __half* W2h = (__half*)(sm + SM_W2H);
    __half* W1A = (__half*)(sm + SM_W1A);
    __half* uBh = (__half*)(sm + SM_UB);
    __half* hTh = (__half*)(sm + SM_HT);

    // ---- stage weights (once) ----
    for (int i = tid; i < 48 * AST / 2; i += NT) ((uint32_t*)(sm + SM_W2H))[i] = 0;
    for (int i = tid; i < 80 * A1ST / 2; i += NT) ((uint32_t*)(sm + SM_W1A))[i] = 0;
    for (int i = tid; i < 8 * UB_SAMP / 2; i += NT) ((uint32_t*)(sm + SM_UB))[i] = 0;
    for (int i = tid; i < 72;  i += NT) b1s[i] = b1[i];
    for (int i = tid; i < 48;  i += NT) {
        b2s[i] = (i < 37) ? b2[i] : 0.f;
        w3s[i] = (i < 37) ? W3[i] : 0.f;
    }
    for (int i = tid; i < 18; i += NT) ((float*)(sm + SM_COEFF))[i] = coeff[i];
    if (tid == 0) ((float*)(sm + SM_B3))[0] = b3[0];
    __syncthreads();
    for (int i = tid; i < 37 * 240; i += NT) {        // W2h[co][d*48+ci]
        int co = i / 240, k = i % 240;
        int ci = k / 5, d = k % 5;
        W2h[co * AST + d * 48 + ci] = __float2half(W2[i]);
    }
    for (int i = tid; i < 72 * 5; i += NT) {          // W1A[c][k], k<5
        int c = i / 5, k = i % 5;
        W1A[c * A1ST + k] = __float2half(W1[i]);
    }
    __syncthreads();

    // conv2 A lane addresses (3 m-tiles)
    uint32_t a_lane[3];
    #pragma unroll
    for (int mt = 0; mt < 3; mt++)
        a_lane[mt] = smb + SM_W2H +
            (uint32_t)(((mt * 16 + (lane & 15)) * AST + ((lane >> 4) << 3)) * 2);
    // conv2 B lane addresses (this warp's sample, halo row = n + d)
    const uint32_t hT_s = smb + SM_HT + (uint32_t)(wid * HT_SAMP * 2);
    const uint32_t b_lane4 = hT_s +
        (uint32_t)((((lane & 7) + ((lane >> 4) & 1) * 8) * HTST + ((lane >> 3) & 1) * 8) * 2);
    const uint32_t b_lane2 = hT_s +
        (uint32_t)(((lane & 7) * HTST + ((lane >> 3) & 1) * 8) * 2);
    // conv1 A / B lane addresses
    const uint32_t a1_lane = smb + SM_W1A +
        (uint32_t)(((lane & 15) * A1ST + ((lane >> 4) << 3)) * 2);
    const uint32_t ub_lane = smb + SM_UB +
        (uint32_t)((wid * UB_SAMP + (lane & 7) * UBST + ((lane >> 3) & 1) * 8) * 2);

    const int g = lane >> 2;            // row within 8-group
    const int q = lane & 3;             // col pair

    // conv1 A fragments + biases are tile-invariant: hoist (20 + 9 regs)
    uint32_t af[5][4];
    #pragma unroll
    for (int mt = 0; mt < 5; mt++)
        ldmatrix_x4(af[mt][0], af[mt][1], af[mt][2], af[mt][3],
                    a1_lane + (uint32_t)(mt * 16 * A1ST * 2));
    float bb[9];
    #pragma unroll
    for (int j = 0; j < 9; j++) bb[j] = b1s[j * 8 + g];

    for (int tile = blockIdx.x; tile < NTILES; tile += GRID) {
        const size_t gsamp = (size_t)tile * NPOS + wid * X;

        // ---- stage u (own sample): fp32 halo + fp16 im2col uB ----
        #pragma unroll
        for (int it = 0; it < 2; it++) {
            int p = lane + it * 32;
            if (p < X) {
                float v = u[gsamp + p];
                float* ur = usf + wid * 44;
                ur[p + 2] = v;
                if (p < 2)   ur[p + 42] = v;
                if (p >= 38) ur[p - 38] = v;
                __half hv = __float2half(v);
                __half* ub = uBh + wid * UB_SAMP;
                #pragma unroll
                for (int d = 0; d < 5; d++) {
                    int row = p - d + 2;
                    row += (row < 0) ? X : 0;
                    row -= (row >= X) ? X : 0;
                    ub[row * UBST + d] = hv;
                }
            }
        }
        __syncwarp();

        // ---- conv1 via HMMA + gate + store hT ----
        {
            __half* ht = hTh + wid * HT_SAMP;
            #pragma unroll
            for (int nt = 0; nt < 5; nt++) {
                uint32_t ub0, ub1;
                ldmatrix_x2(ub0, ub1, ub_lane + (uint32_t)(nt * 8 * UBST * 2));
                float acc1[5][4];
                #pragma unroll
                for (int mt = 0; mt < 5; mt++) {
                    #pragma unroll
                    for (int j = 0; j < 4; j++) acc1[mt][j] = 0.f;
                    mma16816(acc1[mt], af[mt][0], af[mt][1], af[mt][2], af[mt][3], ub0, ub1);
                }
                #pragma unroll
                for (int col = 0; col < 2; col++) {
                    int p = nt * 8 + q * 2 + col;
                    float h0  = fmaxf(acc1[0][col]     + bb[0], 0.f);
                    float h8  = fmaxf(acc1[0][col + 2] + bb[1], 0.f);
                    float h16 = fmaxf(acc1[1][col]     + bb[2], 0.f);
                    float h24 = fmaxf(acc1[1][col + 2] + bb[3], 0.f)
                              * fmaxf(acc1[3][col]     + bb[6], 0.f);
                    float h32 = fmaxf(acc1[2][col]     + bb[4], 0.f)
                              * fmaxf(acc1[3][col + 2] + bb[7], 0.f);
                    float h40 = fmaxf(acc1[2][col + 2] + bb[5], 0.f)
                              * fmaxf(acc1[4][col]     + bb[8], 0.f);
                    __half* hp = ht + (p + 2) * HTST;
                    hp[g]      = __float2half(h0);
                    hp[g + 8]  = __float2half(h8);
                    hp[g + 16] = __float2half(h16);
                    hp[g + 24] = __float2half(h24);
                    hp[g + 32] = __float2half(h32);
                    hp[g + 40] = __float2half(h40);
                    if (p < 2 || p >= 38) {
                        __half* hq = ht + ((p < 2) ? (p + 42) : (p - 38)) * HTST;
                        hq[g]      = __float2half(h0);
                        hq[g + 8]  = __float2half(h8);
                        hq[g + 16] = __float2half(h16);
                        hq[g + 24] = __float2half(h24);
                        hq[g + 32] = __float2half(h32);
                        hq[g + 40] = __float2half(h40);
                    }
                }
            }
        }
        __syncwarp();

        // ---- conv2 GEMM: per kt load B once, 3 A tiles, 15 HMMA ----
        float acc[3][20];
        #pragma unroll
        for (int mt = 0; mt < 3; mt++)
            #pragma unroll
            for (int j = 0; j < 20; j++) acc[mt][j] = 0.f;

        #pragma unroll
        for (int kt = 0; kt < 15; kt++) {
            const int d   = kt / 3;
            const int ci0 = (kt % 3) * 16;
            const uint32_t bofs = (uint32_t)(((d * HTST) + ci0) * 2);

            uint32_t b0, b1_, b2_, b3_;
            ldmatrix_x4(b0, b1_, b2_, b3_, b_lane4 + bofs);
            uint32_t e0, e1, e2, e3;
            ldmatrix_x4(e0, e1, e2, e3, b_lane4 + bofs + (uint32_t)(16 * HTST * 2));
            uint32_t f0, f1;
            ldmatrix_x2(f0, f1, b_lane2 + bofs + (uint32_t)(32 * HTST * 2));

            #pragma unroll
            for (int mt = 0; mt < 3; mt++) {
                uint32_t a0, a1, a2, a3;
                ldmatrix_x4(a0, a1, a2, a3, a_lane[mt] + (uint32_t)(kt * 32));
                mma16816(acc[mt] + 0,  a0, a1, a2, a3, b0, b1_);
                mma16816(acc[mt] + 4,  a0, a1, a2, a3, b2_, b3_);
                mma16816(acc[mt] + 8,  a0, a1, a2, a3, e0, e1);
                mma16816(acc[mt] + 12, a0, a1, a2, a3, e2, e3);
                mma16816(acc[mt] + 16, a0, a1, a2, a3, f0, f1);
            }
        }

        // ---- epilogue: relu(acc+b2)*W3, sum rows, shfl reduce -> part ----
        {
            float b2v[6], w3v[6];
            #pragma unroll
            for (int mt = 0; mt < 3; mt++) {
                b2v[mt*2]   = b2s[mt*16 + g];     w3v[mt*2]   = w3s[mt*16 + g];
                b2v[mt*2+1] = b2s[mt*16 + g + 8]; w3v[mt*2+1] = w3s[mt*16 + g + 8];
            }
            #pragma unroll
            for (int nt = 0; nt < 5; nt++) {
                float t0 = 0.f, t1 = 0.f;
                #pragma unroll
                for (int mt = 0; mt < 3; mt++) {
                    t0 += fmaxf(acc[mt][nt*4+0] + b2v[mt*2],   0.f) * w3v[mt*2]
                        + fmaxf(acc[mt][nt*4+2] + b2v[mt*2+1], 0.f) * w3v[mt*2+1];
                    t1 += fmaxf(acc[mt][nt*4+1] + b2v[mt*2],   0.f) * w3v[mt*2]
                        + fmaxf(acc[mt][nt*4+3] + b2v[mt*2+1], 0.f) * w3v[mt*2+1];
                }
                #pragma unroll
                for (int ofs = 4; ofs <= 16; ofs <<= 1) {
                    t0 += __shfl_xor_sync(0xFFFFFFFF, t0, ofs);
                    t1 += __shfl_xor_sync(0xFFFFFFFF, t1, ofs);
                }
                if (lane < 4) {
                    part[wid * 40 + nt * 8 + lane * 2]     = t0;
                    part[wid * 40 + nt * 8 + lane * 2 + 1] = t1;
                }
            }
        }
        __syncwarp();

        // ---- final (own sample): stencil head + b3 + conv partial ----
        #pragma unroll
        for (int it = 0; it < 2; it++) {
            int p = lane + it * 32;
            if (p < X) {
                const float* ur = usf + wid * 44 + p;
                const float* cf = (const float*)(sm + SM_COEFF);
                float um2 = ur[0], um1 = ur[1], uc = ur[2], up1 = ur[3], up2 = ur[4];
                float o = cf[0];
                o = fmaf(cf[1],  um2,       o);
                o = fmaf(cf[2],  um1,       o);
                o = fmaf(cf[3],  uc,        o);
                o = fmaf(cf[4],  up1,       o);
                o = fmaf(cf[5],  up2,       o);
                o = fmaf(cf[6],  um2 * um2, o);
                o = fmaf(cf[7],  um1 * um1, o);
                o = fmaf(cf[8],  uc  * uc,  o);
                o = fmaf(cf[9],  up1 * up1, o);
                o = fmaf(cf[10], up2 * up2, o);
                o = fmaf(cf[11], um2 * um1, o);
                o = fmaf(cf[12], um1 * uc,  o);
                o = fmaf(cf[13], uc  * up1, o);
                o = fmaf(cf[14], up1 * up2, o);
                o = fmaf(cf[15], um2 * uc,  o);
                o = fmaf(cf[16], um1 * up1, o);
                o = fmaf(cf[17], uc  * up2, o);
                o += ((float*)(sm + SM_B3))[0];
                o += part[wid * 40 + p];
                out[gsamp + p] = o;
            }
        }
        __syncwarp();
    }
}

extern "C" void kernel_launch(void* const* d_in, const int* in_sizes, int n_in,
                              void* d_out, int out_size)
{
    // inputs: 0:t 1:u 2:coeff 3:W1 4:b1 5:W2 6:b2 7:W3 8:b3
    const float* u     = (const float*)d_in[1];
    const float* coeff = (const float*)d_in[2];
    const float* W1    = (const float*)d_in[3];
    const float* b1    = (const float*)d_in[4];
    const float* W2    = (const float*)d_in[5];
    const float* b2    = (const float*)d_in[6];
    const float* W3    = (const float*)d_in[7];
    const float* b3    = (const float*)d_in[8];
    float* out = (float*)d_out;

    cudaFuncSetAttribute(l96_bf_kernel, cudaFuncAttributeMaxDynamicSharedMemorySize, SM_TOTAL);
    l96_bf_kernel<<<GRID, NT, SM_TOTAL>>>(u, coeff, W1, b1, W2, b2, W3, b3, out);
}

// round 13
// speedup vs baseline: 3.5256x; 1.0936x over previous
#include <cuda_runtime.h>
#include <cuda_fp16.h>
#include <cstdint>

// Lorenz96, all-tensor, barrier-free (R13).
// warp = sample end-to-end. conv1 via m16n8k8 HMMA with bias folded into K
// (uB k5 = 1, W1A k5 = b1); h stored channel-interleaved (c_new = 6*(c&7)+(c>>3))
// as 3x STS.32; W2 K-index uses the same permutation. conv2 unchanged from R12:
// D[48pad(37)][40] = W2perm[48][240] x B[240][40] via ldmatrix im2col.

#define NT     256
#define GRID   296
#define X      40
#define SPT    8
#define NPOS   (SPT*X)        // 320
#define NTILES 8192           // 65536 / SPT
#define AST    248            // W2h row stride (halves)
#define HTST   56             // hT row stride (halves)
#define HT_SAMP (44*HTST)     // 2464 halves per sample
#define A1ST   24             // W1A row stride (halves)
#define UBST   8              // uB row stride (halves): k0-4 taps, k5=1, k6-7=0
#define UB_SAMP (40*UBST)     // 320 halves per sample

// smem byte offsets (16B aligned)
#define SM_W2H   0            // 23808
#define SM_HT    23808        // 39424 -> 63232
#define SM_UB    63232        // 5120  -> 68352
#define SM_W1A   68352        // 3840  -> 72192
#define SM_US    72192        // 1408  -> 73600
#define SM_B2    73600        // 192
#define SM_W3    73792        // 192
#define SM_COEFF 73984        // 72
#define SM_B3    74056        // 8
#define SM_PART  74064        // 1280 -> 75344
#define SM_TOTAL 75392

__device__ __forceinline__ uint32_t smem_u32(const void* p) {
    uint32_t a;
    asm("{ .reg .u64 t; cvta.to.shared.u64 t, %1; cvt.u32.u64 %0, t; }" : "=r"(a) : "l"(p));
    return a;
}
__device__ __forceinline__ void ldmatrix_x4(uint32_t& a0, uint32_t& a1, uint32_t& a2, uint32_t& a3,
                                            uint32_t addr) {
    asm volatile("ldmatrix.sync.aligned.m8n8.x4.shared.b16 {%0,%1,%2,%3}, [%4];"
                 : "=r"(a0), "=r"(a1), "=r"(a2), "=r"(a3) : "r"(addr));
}
__device__ __forceinline__ void ldmatrix_x2(uint32_t& a0, uint32_t& a1, uint32_t addr) {
    asm volatile("ldmatrix.sync.aligned.m8n8.x2.shared.b16 {%0,%1}, [%2];"
                 : "=r"(a0), "=r"(a1) : "r"(addr));
}
__device__ __forceinline__ void ldmatrix_x1(uint32_t& a0, uint32_t addr) {
    asm volatile("ldmatrix.sync.aligned.m8n8.x1.shared.b16 {%0}, [%1];"
                 : "=r"(a0) : "r"(addr));
}
__device__ __forceinline__ void mma16816(float* c, uint32_t a0, uint32_t a1, uint32_t a2, uint32_t a3,
                                         uint32_t b0, uint32_t b1) {
    asm volatile("mma.sync.aligned.m16n8k16.row.col.f32.f16.f16.f32 "
                 "{%0,%1,%2,%3}, {%4,%5,%6,%7}, {%8,%9}, {%0,%1,%2,%3};"
                 : "+f"(c[0]), "+f"(c[1]), "+f"(c[2]), "+f"(c[3])
                 : "r"(a0), "r"(a1), "r"(a2), "r"(a3), "r"(b0), "r"(b1));
}
__device__ __forceinline__ void mma16808(float* c, uint32_t a0, uint32_t a1, uint32_t b0) {
    asm volatile("mma.sync.aligned.m16n8k8.row.col.f32.f16.f16.f32 "
                 "{%0,%1,%2,%3}, {%4,%5}, {%6}, {%0,%1,%2,%3};"
                 : "+f"(c[0]), "+f"(c[1]), "+f"(c[2]), "+f"(c[3])
                 : "r"(a0), "r"(a1), "r"(b0));
}
// pack (lo, hi) floats -> half2 in one cvt
__device__ __forceinline__ uint32_t pack_h2(float lo, float hi) {
    uint32_t r;
    asm("cvt.rn.f16x2.f32 %0, %1, %2;" : "=r"(r) : "f"(hi), "f"(lo));
    return r;
}

__global__ __launch_bounds__(NT, 2)
void l96_k8_kernel(const float* __restrict__ u,  const float* __restrict__ coeff,
                   const float* __restrict__ W1, const float* __restrict__ b1,
                   const float* __restrict__ W2, const float* __restrict__ b2,
                   const float* __restrict__ W3, const float* __restrict__ b3,
                   float* __restrict__ out)
{
    extern __shared__ char sm[];
    const uint32_t smb = smem_u32(sm);
    const int tid  = threadIdx.x;
    const int wid  = tid >> 5;      // warp = sample
    const int lane = tid & 31;

    float* b2s  = (float*)(sm + SM_B2);
    float* w3s  = (float*)(sm + SM_W3);
    float* usf  = (float*)(sm + SM_US);
    float* part = (float*)(sm + SM_PART);
    __half* W2h = (__half*)(sm + SM_W2H);
    __half* W1A = (__half*)(sm + SM_W1A);
    __half* uBh = (__half*)(sm + SM_UB);
    __half* hTh = (__half*)(sm + SM_HT);

    // ---- stage weights (once) ----
    for (int i = tid; i < 48 * AST / 2; i += NT) ((uint32_t*)(sm + SM_W2H))[i] = 0;
    for (int i = tid; i < 80 * A1ST / 2; i += NT) ((uint32_t*)(sm + SM_W1A))[i] = 0;
    for (int i = tid; i < 8 * UB_SAMP / 2; i += NT) ((uint32_t*)(sm + SM_UB))[i] = 0;
    for (int i = tid; i < 48;  i += NT) {
        b2s[i] = (i < 37) ? b2[i] : 0.f;
        w3s[i] = (i < 37) ? W3[i] : 0.f;
    }
    for (int i = tid; i < 18; i += NT) ((float*)(sm + SM_COEFF))[i] = coeff[i];
    if (tid == 0) ((float*)(sm + SM_B3))[0] = b3[0];
    __syncthreads();
    // W2h[co][d*48 + cperm(ci)], cperm(ci) = 6*(ci&7) + (ci>>3)
    for (int i = tid; i < 37 * 240; i += NT) {
        int co = i / 240, k = i % 240;
        int ci = k / 5, d = k % 5;
        int cp = 6 * (ci & 7) + (ci >> 3);
        W2h[co * AST + d * 48 + cp] = __float2half(W2[i]);
    }
    // W1A[c][k]: k<5 = W1 taps, k=5 = bias (uB k5 column is 1.0)
    for (int i = tid; i < 72 * 6; i += NT) {
        int c = i / 6, k = i % 6;
        W1A[c * A1ST + k] = __float2half((k < 5) ? W1[c * 5 + k] : b1[c]);
    }
    __syncthreads();

    // conv2 A lane addresses (3 m-tiles)
    uint32_t a_lane[3];
    #pragma unroll
    for (int mt = 0; mt < 3; mt++)
        a_lane[mt] = smb + SM_W2H +
            (uint32_t)(((mt * 16 + (lane & 15)) * AST + ((lane >> 4) << 3)) * 2);
    // conv2 B lane addresses (this warp's sample, halo row = n + d)
    const uint32_t hT_s = smb + SM_HT + (uint32_t)(wid * HT_SAMP * 2);
    const uint32_t b_lane4 = hT_s +
        (uint32_t)((((lane & 7) + ((lane >> 4) & 1) * 8) * HTST + ((lane >> 3) & 1) * 8) * 2);
    const uint32_t b_lane2 = hT_s +
        (uint32_t)(((lane & 7) * HTST + ((lane >> 3) & 1) * 8) * 2);
    // conv1 A (k8: rows 0-15) / B (x1: 8 rows of 8 halves) lane addresses
    const uint32_t a1_lane = smb + SM_W1A + (uint32_t)(((lane & 15) * A1ST) * 2);
    const uint32_t ub_lane = smb + SM_UB +
        (uint32_t)((wid * UB_SAMP + (lane & 7) * UBST) * 2);

    const int g = lane >> 2;            // row within 8-group
    const int q = lane & 3;             // col pair

    // conv1 A fragments tile-invariant (5 m-tiles x 2 regs)
    uint32_t af[5][2];
    #pragma unroll
    for (int mt = 0; mt < 5; mt++)
        ldmatrix_x2(af[mt][0], af[mt][1], a1_lane + (uint32_t)(mt * 16 * A1ST * 2));

    for (int tile = blockIdx.x; tile < NTILES; tile += GRID) {
        const size_t gsamp = (size_t)tile * NPOS + wid * X;

        // ---- stage u (own sample): fp32 halo + fp16 im2col uB + bias col ----
        #pragma unroll
        for (int it = 0; it < 2; it++) {
            int p = lane + it * 32;
            if (p < X) {
                float v = u[gsamp + p];
                float* ur = usf + wid * 44;
                ur[p + 2] = v;
                if (p < 2)   ur[p + 42] = v;
                if (p >= 38) ur[p - 38] = v;
                __half hv = __float2half(v);
                __half* ub = uBh + wid * UB_SAMP;
                #pragma unroll
                for (int d = 0; d < 5; d++) {
                    int row = p - d + 2;
                    row += (row < 0) ? X : 0;
                    row -= (row >= X) ? X : 0;
                    ub[row * UBST + d] = hv;
                }
                ub[p * UBST + 5] = __float2half(1.0f);
            }
        }
        __syncwarp();

        // ---- conv1 via m16n8k8 HMMA + gate + packed hT stores ----
        {
            __half* ht = hTh + wid * HT_SAMP;
            #pragma unroll
            for (int nt = 0; nt < 5; nt++) {
                uint32_t ub0;
                ldmatrix_x1(ub0, ub_lane + (uint32_t)(nt * 8 * UBST * 2));
                float acc1[5][4];
                #pragma unroll
                for (int mt = 0; mt < 5; mt++) {
                    #pragma unroll
                    for (int j = 0; j < 4; j++) acc1[mt][j] = 0.f;
                    mma16808(acc1[mt], af[mt][0], af[mt][1], ub0);
                }
                #pragma unroll
                for (int col = 0; col < 2; col++) {
                    int p = nt * 8 + q * 2 + col;
                    float h0  = fmaxf(acc1[0][col],     0.f);                       // ch g
                    float h8  = fmaxf(acc1[0][col + 2], 0.f);                       // ch g+8
                    float h16 = fmaxf(acc1[1][col],     0.f);                       // ch g+16
                    float h24 = fmaxf(acc1[1][col + 2], 0.f)
                              * fmaxf(acc1[3][col],     0.f);                       // ch g+24
                    float h32 = fmaxf(acc1[2][col],     0.f)
                              * fmaxf(acc1[3][col + 2], 0.f);                       // ch g+32
                    float h40 = fmaxf(acc1[2][col + 2], 0.f)
                              * fmaxf(acc1[4][col],     0.f);                       // ch g+40
                    uint32_t r0 = pack_h2(h0,  h8);
                    uint32_t r1 = pack_h2(h16, h24);
                    uint32_t r2 = pack_h2(h32, h40);
                    uint32_t* hp = (uint32_t*)(ht + (p + 2) * HTST + 6 * g);
                    hp[0] = r0; hp[1] = r1; hp[2] = r2;
                    if (p < 2 || p >= 38) {
                        uint32_t* hq = (uint32_t*)(ht + ((p < 2) ? (p + 42) : (p - 38)) * HTST + 6 * g);
                        hq[0] = r0; hq[1] = r1; hq[2] = r2;
                    }
                }
            }
        }
        __syncwarp();

        // ---- conv2 GEMM: per kt load B once, 3 A tiles, 15 HMMA ----
        float acc[3][20];
        #pragma unroll
        for (int mt = 0; mt < 3; mt++)
            #pragma unroll
            for (int j = 0; j < 20; j++) acc[mt][j] = 0.f;

        #pragma unroll
        for (int kt = 0; kt < 15; kt++) {
            const int d   = kt / 3;
            const int ci0 = (kt % 3) * 16;
            const uint32_t bofs = (uint32_t)(((d * HTST) + ci0) * 2);

            uint32_t b0, b1_, b2_, b3_;
            ldmatrix_x4(b0, b1_, b2_, b3_, b_lane4 + bofs);
            uint32_t e0, e1, e2, e3;
            ldmatrix_x4(e0, e1, e2, e3, b_lane4 + bofs + (uint32_t)(16 * HTST * 2));
            uint32_t f0, f1;
            ldmatrix_x2(f0, f1, b_lane2 + bofs + (uint32_t)(32 * HTST * 2));

            #pragma unroll
            for (int mt = 0; mt < 3; mt++) {
                uint32_t a0, a1, a2, a3;
                ldmatrix_x4(a0, a1, a2, a3, a_lane[mt] + (uint32_t)(kt * 32));
                mma16816(acc[mt] + 0,  a0, a1, a2, a3, b0, b1_);
                mma16816(acc[mt] + 4,  a0, a1, a2, a3, b2_, b3_);
                mma16816(acc[mt] + 8,  a0, a1, a2, a3, e0, e1);
                mma16816(acc[mt] + 12, a0, a1, a2, a3, e2, e3);
                mma16816(acc[mt] + 16, a0, a1, a2, a3, f0, f1);
            }
        }

        // ---- epilogue: relu(acc+b2)*W3, sum rows, shfl reduce -> part ----
        {
            float b2v[6], w3v[6];
            #pragma unroll
            for (int mt = 0; mt < 3; mt++) {
                b2v[mt*2]   = b2s[mt*16 + g];     w3v[mt*2]   = w3s[mt*16 + g];
                b2v[mt*2+1] = b2s[mt*16 + g + 8]; w3v[mt*2+1] = w3s[mt*16 + g + 8];
            }
            #pragma unroll
            for (int nt = 0; nt < 5; nt++) {
                float t0 = 0.f, t1 = 0.f;
                #pragma unroll
                for (int mt = 0; mt < 3; mt++) {
                    t0 += fmaxf(acc[mt][nt*4+0] + b2v[mt*2],   0.f) * w3v[mt*2]
                        + fmaxf(acc[mt][nt*4+2] + b2v[mt*2+1], 0.f) * w3v[mt*2+1];
                    t1 += fmaxf(acc[mt][nt*4+1] + b2v[mt*2],   0.f) * w3v[mt*2]
                        + fmaxf(acc[mt][nt*4+3] + b2v[mt*2+1], 0.f) * w3v[mt*2+1];
                }
                #pragma unroll
                for (int ofs = 4; ofs <= 16; ofs <<= 1) {
                    t0 += __shfl_xor_sync(0xFFFFFFFF, t0, ofs);
                    t1 += __shfl_xor_sync(0xFFFFFFFF, t1, ofs);
                }
                if (lane < 4) {
                    part[wid * 40 + nt * 8 + lane * 2]     = t0;
                    part[wid * 40 + nt * 8 + lane * 2 + 1] = t1;
                }
            }
        }
        __syncwarp();

        // ---- final (own sample): stencil head + b3 + conv partial ----
        #pragma unroll
        for (int it = 0; it < 2; it++) {
            int p = lane + it * 32;
            if (p < X) {
                const float* ur = usf + wid * 44 + p;
                const float* cf = (const float*)(sm + SM_COEFF);
                float um2 = ur[0], um1 = ur[1], uc = ur[2], up1 = ur[3], up2 = ur[4];
                float o = cf[0];
                o = fmaf(cf[1],  um2,       o);
                o = fmaf(cf[2],  um1,       o);
                o = fmaf(cf[3],  uc,        o);
                o = fmaf(cf[4],  up1,       o);
                o = fmaf(cf[5],  up2,       o);
                o = fmaf(cf[6],  um2 * um2, o);
                o = fmaf(cf[7],  um1 * um1, o);
                o = fmaf(cf[8],  uc  * uc,  o);
                o = fmaf(cf[9],  up1 * up1, o);
                o = fmaf(cf[10], up2 * up2, o);
                o = fmaf(cf[11], um2 * um1, o);
                o = fmaf(cf[12], um1 * uc,  o);
                o = fmaf(cf[13], uc  * up1, o);
                o = fmaf(cf[14], up1 * up2, o);
                o = fmaf(cf[15], um2 * uc,  o);
                o = fmaf(cf[16], um1 * up1, o);
                o = fmaf(cf[17], uc  * up2, o);
                o += ((float*)(sm + SM_B3))[0];
                o += part[wid * 40 + p];
                out[gsamp + p] = o;
            }
        }
        __syncwarp();
    }
}

extern "C" void kernel_launch(void* const* d_in, const int* in_sizes, int n_in,
                              void* d_out, int out_size)
{
    // inputs: 0:t 1:u 2:coeff 3:W1 4:b1 5:W2 6:b2 7:W3 8:b3
    const float* u     = (const float*)d_in[1];
    const float* coeff = (const float*)d_in[2];
    const float* W1    = (const float*)d_in[3];
    const float* b1    = (const float*)d_in[4];
    const float* W2    = (const float*)d_in[5];
    const float* b2    = (const float*)d_in[6];
    const float* W3    = (const float*)d_in[7];
    const float* b3    = (const float*)d_in[8];
    float* out = (float*)d_out;

    cudaFuncSetAttribute(l96_k8_kernel, cudaFuncAttributeMaxDynamicSharedMemorySize, SM_TOTAL);
    l96_k8_kernel<<<GRID, NT, SM_TOTAL>>>(u, coeff, W1, b1, W2, b2, W3, b3, out);
}